// round 1
// baseline (speedup 1.0000x reference)
#include <cuda_runtime.h>
#include <math.h>
#include <stdint.h>

// Problem constants
#define BB   8
#define LL   8192
#define CC   256
#define PE   96
#define RR   90
#define UP   4
#define OUTC 256
#define KK   448            // CC + 2*PE
#define NN   1024           // OUTC * UP
#define MM   (BB * LL)      // 65536 rows

#define FC_GAIN      0.04724555912615336f   // 1/sqrt(448)
#define SQRT2_F      1.4142135623730951f
#define INV_SQRT2_F  0.7071067811865476f
#define INV_SQRT3_F  0.5773502691896258f

// Scratch: x_pe rows [MM, KK] fp32 (117 MB). Static device array (no allocs allowed).
__device__ float g_xpe[(size_t)MM * KK];

// ---------------------------------------------------------------------------
// Kernel 1: build x_pe = [x | sin(LFF(pc)) | const_PE(pc)] per row.
// One block (128 threads) per row; trivially memory-bound (~180 MB traffic).
// ---------------------------------------------------------------------------
__global__ __launch_bounds__(128) void build_xpe_kernel(
    const float* __restrict__ x,
    const float* __restrict__ pc,
    const float* __restrict__ lff_w,
    const float* __restrict__ lff_b,
    const float* __restrict__ cpe_tab)   // const_pe [3, PE, RR]
{
    const int r = blockIdx.x;        // 0..MM-1
    const int t = threadIdx.x;       // 0..127
    const float* xr = x + (size_t)r * CC;
    float* out = g_xpe + (size_t)r * KK;

    const float p0 = pc[r * 3 + 0];
    const float p1 = pc[r * 3 + 1];
    const float p2 = pc[r * 3 + 2];

    // copy x row (256 floats) as 64 float4
    if (t < 64) {
        reinterpret_cast<float4*>(out)[t] =
            reinterpret_cast<const float4*>(xr)[t];
    }

    if (t < PE) {
        // LFF positional encoding: sin(pc . w_d + b_d)
        float s = fmaf(p0, lff_w[t * 3 + 0],
                  fmaf(p1, lff_w[t * 3 + 1],
                  fmaf(p2, lff_w[t * 3 + 2], lff_b[t])));
        out[CC + t] = sinf(s);

        // constant PE: bilinear gather along width, zero padding, sum channels / sqrt(3)
        float pcv[3] = {p0, p1, p2};
        float acc = 0.0f;
        #pragma unroll
        for (int ch = 0; ch < 3; ch++) {
            float ix  = ((pcv[ch] + 1.0f) * (float)RR - 1.0f) * 0.5f;
            float fi0 = floorf(ix);
            float w   = ix - fi0;
            int   i0  = (int)fi0;
            int   i1  = i0 + 1;
            const float* row = cpe_tab + ((size_t)ch * PE + t) * RR;
            float v0 = (i0 >= 0 && i0 < RR) ? row[i0] : 0.0f;
            float v1 = (i1 >= 0 && i1 < RR) ? row[i1] : 0.0f;
            acc += v0 * (1.0f - w) + v1 * w;
        }
        out[CC + PE + t] = acc * INV_SQRT3_F;
    }
}

// ---------------------------------------------------------------------------
// Kernel 2: GEMM y[M,N] = x_pe[M,K] * sub_w[N,K]^T with fused epilogue:
//   y = y*gain + bias ; lrelu(0.2)*sqrt(2) ; out = (x_res + act)/sqrt(2)
//   scattered to x_up[b, l*4+u, c] layout (o = u*256 + c).
// Classic 128x128 tile, BK=8, 256 threads, 8x8 per-thread microtile.
// ---------------------------------------------------------------------------
#define BM 128
#define BN 128
#define BK 8
#define TM 8
#define TN 8

__global__ __launch_bounds__(256) void gemm_fused_kernel(
    const float* __restrict__ x,       // residual source [MM, 256]
    const float* __restrict__ sub_w,   // [NN, KK]
    const float* __restrict__ sub_b,   // [NN]
    float* __restrict__ out_xup)       // [BB, LL*UP, OUTC]
{
    __shared__ float As[BK][BM];
    __shared__ float Bs[BK][BN];

    const int m0 = blockIdx.y * BM;
    const int n0 = blockIdx.x * BN;
    const int tid = threadIdx.x;
    const int trow = tid / 16;          // 0..15
    const int tcol = tid % 16;          // 0..15

    const float* A  = g_xpe + (size_t)m0 * KK;
    const float* Bp = sub_w + (size_t)n0 * KK;

    // load mapping: 256 threads, each one float4 per matrix per BK step
    const int aRow  = tid >> 1;         // 0..127
    const int aCol4 = (tid & 1) * 4;    // 0 or 4

    float acc[TM][TN];
    #pragma unroll
    for (int i = 0; i < TM; i++)
        #pragma unroll
        for (int j = 0; j < TN; j++) acc[i][j] = 0.0f;

    for (int k0 = 0; k0 < KK; k0 += BK) {
        float4 av = *reinterpret_cast<const float4*>(A  + (size_t)aRow * KK + k0 + aCol4);
        float4 bv = *reinterpret_cast<const float4*>(Bp + (size_t)aRow * KK + k0 + aCol4);
        As[aCol4 + 0][aRow] = av.x;
        As[aCol4 + 1][aRow] = av.y;
        As[aCol4 + 2][aRow] = av.z;
        As[aCol4 + 3][aRow] = av.w;
        Bs[aCol4 + 0][aRow] = bv.x;
        Bs[aCol4 + 1][aRow] = bv.y;
        Bs[aCol4 + 2][aRow] = bv.z;
        Bs[aCol4 + 3][aRow] = bv.w;
        __syncthreads();

        #pragma unroll
        for (int k = 0; k < BK; k++) {
            float rm[TM], rn[TN];
            #pragma unroll
            for (int i = 0; i < TM; i++) rm[i] = As[k][trow * TM + i];
            #pragma unroll
            for (int j = 0; j < TN; j++) rn[j] = Bs[k][tcol * TN + j];
            #pragma unroll
            for (int i = 0; i < TM; i++)
                #pragma unroll
                for (int j = 0; j < TN; j++)
                    acc[i][j] = fmaf(rm[i], rn[j], acc[i][j]);
        }
        __syncthreads();
    }

    // Epilogue: bias, lrelu, residual, scatter.
    #pragma unroll
    for (int i = 0; i < TM; i++) {
        const int r = m0 + trow * TM + i;     // global row in [0, MM)
        const int b = r >> 13;                // r / LL
        const int l = r & (LL - 1);
        #pragma unroll
        for (int j = 0; j < TN; j++) {
            const int o = n0 + tcol * TN + j; // 0..1023
            const int u = o >> 8;             // 0..3
            const int c = o & 255;
            float y = fmaf(acc[i][j], FC_GAIN, sub_b[o]);
            float act = (y >= 0.0f ? y : 0.2f * y) * SQRT2_F;
            float xv = x[(size_t)r * CC + c];
            size_t oidx = (((size_t)b * (LL * UP)) + (size_t)l * UP + u) * OUTC + c;
            out_xup[oidx] = (xv + act) * INV_SQRT2_F;
        }
    }
}

// ---------------------------------------------------------------------------
// Kernel 3: pc_up = repeat_interleave(pc, 4, axis=1)
// ---------------------------------------------------------------------------
__global__ __launch_bounds__(256) void pc_up_kernel(
    const float* __restrict__ pc,
    float* __restrict__ out_pc)
{
    int idx = blockIdx.x * blockDim.x + threadIdx.x;
    const int total = MM * UP * 3;
    if (idx < total) {
        int k  = idx % 3;
        int ru = idx / 3;       // (b*LL + l)*UP + u
        int r  = ru >> 2;       // b*LL + l
        out_pc[idx] = pc[r * 3 + k];
    }
}

// ---------------------------------------------------------------------------
extern "C" void kernel_launch(void* const* d_in, const int* in_sizes, int n_in,
                              void* d_out, int out_size)
{
    const float* x       = (const float*)d_in[0]; // [8, 8192, 256]
    const float* pc      = (const float*)d_in[1]; // [8, 8192, 3]
    const float* lff_w   = (const float*)d_in[2]; // [96, 3]
    const float* lff_b   = (const float*)d_in[3]; // [96]
    const float* cpe_tab = (const float*)d_in[4]; // [3, 96, 90]
    const float* sub_w   = (const float*)d_in[5]; // [1024, 448]
    const float* sub_b   = (const float*)d_in[6]; // [1024]

    float* out_xup = (float*)d_out;                          // [8, 32768, 256]
    float* out_pc  = (float*)d_out + (size_t)MM * UP * OUTC; // [8, 32768, 3]

    build_xpe_kernel<<<MM, 128>>>(x, pc, lff_w, lff_b, cpe_tab);

    dim3 grid(NN / BN, MM / BM);   // (8, 512)
    gemm_fused_kernel<<<grid, 256>>>(x, sub_w, sub_b, out_xup);

    const int total_pc = MM * UP * 3;
    pc_up_kernel<<<(total_pc + 255) / 256, 256>>>(pc, out_pc);
}

// round 2
// speedup vs baseline: 3.2135x; 3.2135x over previous
#include <cuda_runtime.h>
#include <math.h>
#include <stdint.h>

// Problem constants
#define BB   8
#define LL   8192
#define CC   256
#define PEC  96
#define RR   90
#define UP   4
#define OUTC 256
#define KK   448            // CC + 2*PEC
#define NN   1024           // OUTC * UP
#define MM   (BB * LL)      // 65536 rows
#define PEW  192            // 2*PEC  (PE scratch width)

#define FC_GAIN      0.04724555912615336f   // 1/sqrt(448)
#define SQRT2_F      1.4142135623730951f
#define INV_SQRT2_F  0.7071067811865476f
#define INV_SQRT3_F  0.5773502691896258f

// Scratch: PE part of x_pe only: [MM, 192] fp32 (50 MB).
__device__ float g_pe[(size_t)MM * PEW];

__device__ __forceinline__ uint32_t f2tf32(float f) {
    uint32_t o;
    asm("cvt.rna.tf32.f32 %0, %1;" : "=r"(o) : "f"(f));
    return o;
}

// ---------------------------------------------------------------------------
// Kernel 1: build PE columns [sin(LFF(pc)) | const_PE(pc)] (192 per row)
// and pc_up = repeat_interleave(pc, 4).
// ---------------------------------------------------------------------------
__global__ __launch_bounds__(128) void build_pe_kernel(
    const float* __restrict__ pc,
    const float* __restrict__ lff_w,
    const float* __restrict__ lff_b,
    const float* __restrict__ cpe_tab,   // const_pe [3, PEC, RR]
    float* __restrict__ out_pc)          // [BB, LL*UP, 3]
{
    const int r = blockIdx.x;        // 0..MM-1
    const int t = threadIdx.x;       // 0..127
    float* out = g_pe + (size_t)r * PEW;

    const float p0 = pc[r * 3 + 0];
    const float p1 = pc[r * 3 + 1];
    const float p2 = pc[r * 3 + 2];

    if (t < PEC) {
        // LFF positional encoding: sin(pc . w_d + b_d)
        float s = fmaf(p0, lff_w[t * 3 + 0],
                  fmaf(p1, lff_w[t * 3 + 1],
                  fmaf(p2, lff_w[t * 3 + 2], lff_b[t])));
        out[t] = sinf(s);

        // constant PE: bilinear gather along width, zero padding, /sqrt(3)
        float pcv[3] = {p0, p1, p2};
        float acc = 0.0f;
        #pragma unroll
        for (int ch = 0; ch < 3; ch++) {
            float ix  = ((pcv[ch] + 1.0f) * (float)RR - 1.0f) * 0.5f;
            float fi0 = floorf(ix);
            float w   = ix - fi0;
            int   i0  = (int)fi0;
            int   i1  = i0 + 1;
            const float* row = cpe_tab + ((size_t)ch * PEC + t) * RR;
            float v0 = (i0 >= 0 && i0 < RR) ? row[i0] : 0.0f;
            float v1 = (i1 >= 0 && i1 < RR) ? row[i1] : 0.0f;
            acc += v0 * (1.0f - w) + v1 * w;
        }
        out[PEC + t] = acc * INV_SQRT3_F;
    } else if (t < PEC + 12) {
        // pc_up: 4 copies of the 3 coords
        int s = t - PEC;            // 0..11
        int u = s >> 2;             // wrong order? s = u*3 + k mapping below
        // use s = u*3+k with u = s/3, k = s%3
        u = s / 3;
        int k = s - u * 3;
        float v = (k == 0) ? p0 : (k == 1) ? p1 : p2;
        out_pc[((size_t)r * UP + u) * 3 + k] = v;
    }
}

// ---------------------------------------------------------------------------
// Kernel 2: TF32 tensor-core GEMM  y[M,N] = A[M,K] * W[N,K]^T, fused epilogue.
// A cols [0,256) come straight from x; cols [256,448) from g_pe.
// CTA tile 128x128, BK=32, 8 warps each 64x32, mma.sync.m16n8k8 tf32.
// ---------------------------------------------------------------------------
__global__ __launch_bounds__(256) void gemm_tf32_kernel(
    const float* __restrict__ x,       // [MM, 256] (A part 1 + residual)
    const float* __restrict__ sub_w,   // [NN, KK]
    const float* __restrict__ sub_b,   // [NN]
    float* __restrict__ out_xup)       // [BB, LL*UP, OUTC]
{
    __shared__ uint32_t As[128][36];   // [m][k] tf32, stride 36 -> conflict-free frag loads
    __shared__ uint32_t Bs[128][36];   // [n][k] tf32

    const int tid  = threadIdx.x;
    const int wid  = tid >> 5;
    const int lane = tid & 31;
    const int grp  = lane >> 2;        // 0..7
    const int qid  = lane & 3;         // 0..3
    const int wm   = wid >> 2;         // 0..1  (64-row slab)
    const int wn   = wid & 3;          // 0..3  (32-col slab)

    const int m0 = blockIdx.y * 128;
    const int n0 = blockIdx.x * 128;

    // global->smem loader mapping: 256 threads, 4 float4 each per tile
    const int lrow = tid >> 3;          // 0..31
    const int lc4  = (tid & 7) * 4;     // 0,4,...,28

    float acc[4][4][4];
    #pragma unroll
    for (int mt = 0; mt < 4; mt++)
        #pragma unroll
        for (int nt = 0; nt < 4; nt++)
            #pragma unroll
            for (int q = 0; q < 4; q++) acc[mt][nt][q] = 0.0f;

    for (int k0 = 0; k0 < KK; k0 += 32) {
        // ---- stage tile to registers (overlaps with previous compute) ----
        float4 av[4], bv[4];
        if (k0 < CC) {
            const float* Ap = x + (size_t)m0 * CC + k0;
            #pragma unroll
            for (int i = 0; i < 4; i++)
                av[i] = *reinterpret_cast<const float4*>(
                    Ap + (size_t)(lrow + 32 * i) * CC + lc4);
        } else {
            const float* Ap = g_pe + (size_t)m0 * PEW + (k0 - CC);
            #pragma unroll
            for (int i = 0; i < 4; i++)
                av[i] = *reinterpret_cast<const float4*>(
                    Ap + (size_t)(lrow + 32 * i) * PEW + lc4);
        }
        {
            const float* Bp = sub_w + (size_t)n0 * KK + k0;
            #pragma unroll
            for (int i = 0; i < 4; i++)
                bv[i] = *reinterpret_cast<const float4*>(
                    Bp + (size_t)(lrow + 32 * i) * KK + lc4);
        }

        __syncthreads();   // previous iteration's compute done
        #pragma unroll
        for (int i = 0; i < 4; i++) {
            int r = lrow + 32 * i;
            As[r][lc4 + 0] = f2tf32(av[i].x);
            As[r][lc4 + 1] = f2tf32(av[i].y);
            As[r][lc4 + 2] = f2tf32(av[i].z);
            As[r][lc4 + 3] = f2tf32(av[i].w);
            Bs[r][lc4 + 0] = f2tf32(bv[i].x);
            Bs[r][lc4 + 1] = f2tf32(bv[i].y);
            Bs[r][lc4 + 2] = f2tf32(bv[i].z);
            Bs[r][lc4 + 3] = f2tf32(bv[i].w);
        }
        __syncthreads();

        // ---- compute: 4 k-steps of 8 ----
        #pragma unroll
        for (int kt = 0; kt < 4; kt++) {
            uint32_t a[4][4], b[4][2];
            const int kc = kt * 8 + qid;
            #pragma unroll
            for (int mt = 0; mt < 4; mt++) {
                int r = wm * 64 + mt * 16 + grp;
                a[mt][0] = As[r][kc];
                a[mt][1] = As[r + 8][kc];
                a[mt][2] = As[r][kc + 4];
                a[mt][3] = As[r + 8][kc + 4];
            }
            #pragma unroll
            for (int nt = 0; nt < 4; nt++) {
                int r = wn * 32 + nt * 8 + grp;
                b[nt][0] = Bs[r][kc];
                b[nt][1] = Bs[r][kc + 4];
            }
            #pragma unroll
            for (int mt = 0; mt < 4; mt++)
                #pragma unroll
                for (int nt = 0; nt < 4; nt++)
                    asm volatile(
                        "mma.sync.aligned.m16n8k8.row.col.f32.tf32.tf32.f32 "
                        "{%0,%1,%2,%3}, {%4,%5,%6,%7}, {%8,%9}, {%0,%1,%2,%3};"
                        : "+f"(acc[mt][nt][0]), "+f"(acc[mt][nt][1]),
                          "+f"(acc[mt][nt][2]), "+f"(acc[mt][nt][3])
                        : "r"(a[mt][0]), "r"(a[mt][1]), "r"(a[mt][2]), "r"(a[mt][3]),
                          "r"(b[nt][0]), "r"(b[nt][1]));
        }
    }

    // ---- fused epilogue: gain, bias, lrelu*sqrt2, residual, /sqrt2, scatter ----
    #pragma unroll
    for (int mt = 0; mt < 4; mt++) {
        #pragma unroll
        for (int rh = 0; rh < 2; rh++) {
            const int m  = m0 + wm * 64 + mt * 16 + grp + rh * 8;
            const int b_ = m >> 13;               // m / LL
            const int l  = m & (LL - 1);
            float* obase = out_xup + ((size_t)b_ * (LL * UP) + (size_t)l * UP) * OUTC;
            const float* xrow = x + (size_t)m * CC;
            #pragma unroll
            for (int nt = 0; nt < 4; nt++) {
                const int o = n0 + wn * 32 + nt * 8 + 2 * qid;  // even, o+1 same u-block
                const int u = o >> 8;
                const int c = o & 255;
                float2 bias = *reinterpret_cast<const float2*>(sub_b + o);
                float2 xres = *reinterpret_cast<const float2*>(xrow + c);
                float y0 = fmaf(acc[mt][nt][rh * 2 + 0], FC_GAIN, bias.x);
                float y1 = fmaf(acc[mt][nt][rh * 2 + 1], FC_GAIN, bias.y);
                float a0 = (y0 >= 0.0f ? y0 : 0.2f * y0) * SQRT2_F;
                float a1 = (y1 >= 0.0f ? y1 : 0.2f * y1) * SQRT2_F;
                float2 ov;
                ov.x = (xres.x + a0) * INV_SQRT2_F;
                ov.y = (xres.y + a1) * INV_SQRT2_F;
                *reinterpret_cast<float2*>(obase + (size_t)u * OUTC + c) = ov;
            }
        }
    }
}

// ---------------------------------------------------------------------------
extern "C" void kernel_launch(void* const* d_in, const int* in_sizes, int n_in,
                              void* d_out, int out_size)
{
    const float* x       = (const float*)d_in[0]; // [8, 8192, 256]
    const float* pc      = (const float*)d_in[1]; // [8, 8192, 3]
    const float* lff_w   = (const float*)d_in[2]; // [96, 3]
    const float* lff_b   = (const float*)d_in[3]; // [96]
    const float* cpe_tab = (const float*)d_in[4]; // [3, 96, 90]
    const float* sub_w   = (const float*)d_in[5]; // [1024, 448]
    const float* sub_b   = (const float*)d_in[6]; // [1024]

    float* out_xup = (float*)d_out;                          // [8, 32768, 256]
    float* out_pc  = (float*)d_out + (size_t)MM * UP * OUTC; // [8, 32768, 3]

    build_pe_kernel<<<MM, 128>>>(pc, lff_w, lff_b, cpe_tab, out_pc);

    dim3 grid(NN / 128, MM / 128);   // (8, 512)
    gemm_tf32_kernel<<<grid, 256>>>(x, sub_w, sub_b, out_xup);
}

// round 4
// speedup vs baseline: 5.8183x; 1.8106x over previous
#include <cuda_runtime.h>
#include <cuda_fp16.h>
#include <math.h>
#include <stdint.h>

// ---------------- problem constants ----------------
#define BB   8
#define LL   8192
#define CC   256
#define PEC  96
#define RR   90
#define UP   4
#define OUTC 256
#define KK   448
#define NN   1024
#define MM   (BB * LL)       // 65536

#define FC_GAIN      0.04724555912615336f   // 1/sqrt(448)
#define SQRT2_F      1.4142135623730951f
#define INV_SQRT2_F  0.7071067811865476f
#define INV_SQRT3_F  0.5773502691896258f

// ---------------- tiling ----------------
#define NCHUNK  14          // K chunks of 32
#define MTILES  512         // M/128
#define NBLKS   8           // N/128
// A block per (mtile, chunk): 128 rows x 32 k fp16, fragment order = 8KB
// B block per (nblk, chunk):  128 n x 32 k fp16, fragment order = 8KB
__device__ uint4 g_Afrag[(size_t)MTILES * NCHUNK * 512];   // ~59 MB
__device__ uint4 g_Bfrag[(size_t)NBLKS * NCHUNK * 512];    // ~0.9 MB

__device__ __forceinline__ uint32_t pkh2(float a, float b) {
    __half2 h = __floats2half2_rn(a, b);        // low = a, high = b
    return *reinterpret_cast<uint32_t*>(&h);
}
__device__ __forceinline__ uint32_t smem_u32(const void* p) {
    uint32_t a;
    asm("{ .reg .u64 t; cvta.to.shared.u64 t, %1; cvt.u32.u64 %0, t; }" : "=r"(a) : "l"(p));
    return a;
}
__device__ __forceinline__ void cp16(uint32_t dst, const void* src) {
    asm volatile("cp.async.cg.shared.global [%0], [%1], 16;" :: "r"(dst), "l"(src) : "memory");
}
__device__ __forceinline__ void cp_commit() { asm volatile("cp.async.commit_group;" ::: "memory"); }
__device__ __forceinline__ void cp_wait1()  { asm volatile("cp.async.wait_group 1;" ::: "memory"); }
__device__ __forceinline__ void cp_wait0()  { asm volatile("cp.async.wait_group 0;" ::: "memory"); }

// ---------------------------------------------------------------------------
// prep A (PE part): one CTA per m16-tile (16 rows). Computes sin-LFF + const-PE
// for 16 rows and writes chunks 8..13 fragments. Also writes pc_up.
// ---------------------------------------------------------------------------
__global__ __launch_bounds__(128) void pe_prep(
    const float* __restrict__ pc,
    const float* __restrict__ lff_w,
    const float* __restrict__ lff_b,
    const float* __restrict__ cpe_tab,   // [3, PEC, RR]
    float* __restrict__ out_pc)          // [BB, LL*UP, 3]
{
    __shared__ float spe[16][192];
    const int t   = threadIdx.x;
    const int m0  = blockIdx.x * 16;
    const int row = t & 15;
    const int dsl = t >> 4;              // 0..7
    const int gm  = m0 + row;

    const float p0 = pc[gm * 3 + 0];
    const float p1 = pc[gm * 3 + 1];
    const float p2 = pc[gm * 3 + 2];
    const float pcv[3] = {p0, p1, p2};

    #pragma unroll
    for (int jj = 0; jj < 12; jj++) {
        const int d = dsl + 8 * jj;      // 0..95, each once
        float s = fmaf(p0, lff_w[d * 3 + 0],
                  fmaf(p1, lff_w[d * 3 + 1],
                  fmaf(p2, lff_w[d * 3 + 2], lff_b[d])));
        spe[row][d] = sinf(s);

        float acc = 0.0f;
        #pragma unroll
        for (int ch = 0; ch < 3; ch++) {
            float ix  = ((pcv[ch] + 1.0f) * (float)RR - 1.0f) * 0.5f;
            float fi0 = floorf(ix);
            float w   = ix - fi0;
            int   i0  = (int)fi0;
            int   i1  = i0 + 1;
            const float* tr = cpe_tab + ((size_t)ch * PEC + d) * RR;
            float v0 = (i0 >= 0 && i0 < RR) ? tr[i0] : 0.0f;
            float v1 = (i1 >= 0 && i1 < RR) ? tr[i1] : 0.0f;
            acc += v0 * (1.0f - w) + v1 * w;
        }
        spe[row][PEC + d] = acc * INV_SQRT3_F;
    }

    // pc_up: 12 values per row; dsl 0..5 write two each
    if (dsl < 6) {
        #pragma unroll
        for (int q = 0; q < 2; q++) {
            int it = dsl * 2 + q;        // 0..11
            int u  = it >> 2;            // NOTE: layout u*3+k: it = u*3+k
            u = it / 3;
            int k = it - u * 3;
            float v = (k == 0) ? p0 : (k == 1) ? p1 : p2;
            out_pc[((size_t)gm * UP + u) * 3 + k] = v;
        }
    }
    __syncthreads();

    // fragment writes for chunks 8..13
    const int mt  = m0 >> 7;
    const int m16 = (m0 & 127) >> 4;
    #pragma unroll
    for (int j = 0; j < 3; j++) {
        const int fid  = j * 128 + t;    // 0..383
        const int lane = fid & 31;
        const int ks   = (fid >> 5) & 1;
        const int ch   = fid >> 6;       // 0..5
        const int grp  = lane >> 2;
        const int qid  = lane & 3;
        const int c0   = ch * 32 + ks * 16 + 2 * qid;
        uint4 o;
        o.x = pkh2(spe[grp][c0],     spe[grp][c0 + 1]);
        o.y = pkh2(spe[grp + 8][c0], spe[grp + 8][c0 + 1]);
        o.z = pkh2(spe[grp][c0 + 8], spe[grp][c0 + 9]);
        o.w = pkh2(spe[grp + 8][c0 + 8], spe[grp + 8][c0 + 9]);
        const int chunk = 8 + ch;
        g_Afrag[((size_t)mt * NCHUNK + chunk) * 512 + (m16 * 2 + ks) * 32 + lane] = o;
    }
}

// ---------------------------------------------------------------------------
// prep A (x part): one CTA per (chunk 0..7, mtile). Stage 128x32 tile via smem,
// emit fragment-ordered fp16.
// ---------------------------------------------------------------------------
__global__ __launch_bounds__(128) void a_prep(const float* __restrict__ x)
{
    __shared__ float s[128][36];
    const int t     = threadIdx.x;
    const int chunk = blockIdx.x;        // 0..7
    const int mt    = blockIdx.y;        // 0..511
    const int m0    = mt * 128;
    const int k0    = chunk * 32;

    #pragma unroll
    for (int j = 0; j < 8; j++) {
        const int id  = j * 128 + t;
        const int row = id >> 3;
        const int c4  = (id & 7) * 4;
        float4 v = *reinterpret_cast<const float4*>(
            x + (size_t)(m0 + row) * CC + k0 + c4);
        *reinterpret_cast<float4*>(&s[row][c4]) = v;
    }
    __syncthreads();

    #pragma unroll
    for (int j = 0; j < 4; j++) {
        const int fid  = j * 128 + t;    // (m16*2+ks)*32+lane
        const int lane = fid & 31;
        const int ks   = (fid >> 5) & 1;
        const int m16  = fid >> 6;
        const int grp  = lane >> 2;
        const int qid  = lane & 3;
        const int r0   = m16 * 16 + grp;
        const int c0   = ks * 16 + 2 * qid;
        uint4 o;
        o.x = pkh2(s[r0][c0],     s[r0][c0 + 1]);
        o.y = pkh2(s[r0 + 8][c0], s[r0 + 8][c0 + 1]);
        o.z = pkh2(s[r0][c0 + 8], s[r0][c0 + 9]);
        o.w = pkh2(s[r0 + 8][c0 + 8], s[r0 + 8][c0 + 9]);
        g_Afrag[((size_t)mt * NCHUNK + chunk) * 512 + fid] = o;
    }
}

// ---------------------------------------------------------------------------
// prep B: one CTA per (chunk, nblk). Direct gather, tiny.
// ---------------------------------------------------------------------------
__global__ __launch_bounds__(128) void b_prep(const float* __restrict__ sub_w)
{
    const int t     = threadIdx.x;
    const int chunk = blockIdx.x;        // 0..13
    const int nb    = blockIdx.y;        // 0..7
    uint2* dst = reinterpret_cast<uint2*>(g_Bfrag + ((size_t)nb * NCHUNK + chunk) * 512);

    #pragma unroll
    for (int j = 0; j < 8; j++) {
        const int fid  = j * 128 + t;    // (n8*2+ks)*32+lane, 0..1023
        const int lane = fid & 31;
        const int ks   = (fid >> 5) & 1;
        const int n8   = fid >> 6;       // 0..15
        const int grp  = lane >> 2;
        const int qid  = lane & 3;
        const int n    = nb * 128 + n8 * 8 + grp;
        const int k    = chunk * 32 + ks * 16 + 2 * qid;
        float2 v01 = *reinterpret_cast<const float2*>(sub_w + (size_t)n * KK + k);
        float2 v23 = *reinterpret_cast<const float2*>(sub_w + (size_t)n * KK + k + 8);
        uint2 o;
        o.x = pkh2(v01.x, v01.y);
        o.y = pkh2(v23.x, v23.y);
        dst[fid] = o;
    }
}

// ---------------------------------------------------------------------------
// GEMM: fp16 mma.sync m16n8k16, CTA 128x128, BK=32, 3-stage cp.async pipeline.
// 8 warps: wm in {0,1} (64 rows), wn in {0..3} (32 cols).
// ---------------------------------------------------------------------------
__global__ __launch_bounds__(256, 2) void gemm_hmma(
    const float* __restrict__ x,
    const float* __restrict__ sub_b,
    float* __restrict__ out_xup)
{
    __shared__ __align__(16) char smem[49152];   // 3 stages x (A 8KB + B 8KB)
    const uint32_t sb = smem_u32(smem);

    const int tid  = threadIdx.x;
    const int wid  = tid >> 5;
    const int lane = tid & 31;
    const int grp  = lane >> 2;
    const int qid  = lane & 3;
    const int wm   = wid >> 2;
    const int wn   = wid & 3;
    const int nb   = blockIdx.x;     // 0..7
    const int mt   = blockIdx.y;     // 0..511

    const char* gA = (const char*)(g_Afrag + (size_t)mt * NCHUNK * 512);
    const char* gB = (const char*)(g_Bfrag + (size_t)nb * NCHUNK * 512);

    float acc[4][4][4];
    #pragma unroll
    for (int i = 0; i < 4; i++)
        #pragma unroll
        for (int j = 0; j < 4; j++)
            #pragma unroll
            for (int q = 0; q < 4; q++) acc[i][j][q] = 0.0f;

    // issue one chunk into stage s
    #define ISSUE(c, s) do { \
        const char* a_ = gA + (size_t)(c) * 8192; \
        const char* b_ = gB + (size_t)(c) * 8192; \
        uint32_t dA = sb + (s) * 16384; \
        uint32_t dB = dA + 8192; \
        cp16(dA + tid * 16,         a_ + tid * 16); \
        cp16(dA + (tid + 256) * 16, a_ + (tid + 256) * 16); \
        cp16(dB + tid * 16,         b_ + tid * 16); \
        cp16(dB + (tid + 256) * 16, b_ + (tid + 256) * 16); \
        cp_commit(); \
    } while (0)

    ISSUE(0, 0);
    ISSUE(1, 1);

    int stage = 0;
    for (int i = 0; i < NCHUNK; i++) {
        if (i < NCHUNK - 1) cp_wait1(); else cp_wait0();
        __syncthreads();
        if (i + 2 < NCHUNK) {
            int ns = stage + 2; if (ns >= 3) ns -= 3;
            ISSUE(i + 2, ns);
        }

        const uint32_t aBase = sb + stage * 16384;
        const uint32_t bBase = aBase + 8192;
        #pragma unroll
        for (int ks = 0; ks < 2; ks++) {
            uint32_t a[4][4], b[4][2];
            #pragma unroll
            for (int m8 = 0; m8 < 4; m8++) {
                uint32_t ad = aBase + (((wm * 4 + m8) * 2 + ks) * 32 + lane) * 16;
                asm volatile("ld.shared.v4.b32 {%0,%1,%2,%3}, [%4];"
                    : "=r"(a[m8][0]), "=r"(a[m8][1]), "=r"(a[m8][2]), "=r"(a[m8][3])
                    : "r"(ad));
            }
            #pragma unroll
            for (int n8 = 0; n8 < 4; n8++) {
                uint32_t bd = bBase + (((wn * 4 + n8) * 2 + ks) * 32 + lane) * 8;
                asm volatile("ld.shared.v2.b32 {%0,%1}, [%2];"
                    : "=r"(b[n8][0]), "=r"(b[n8][1]) : "r"(bd));
            }
            #pragma unroll
            for (int m8 = 0; m8 < 4; m8++)
                #pragma unroll
                for (int n8 = 0; n8 < 4; n8++)
                    asm volatile(
                        "mma.sync.aligned.m16n8k16.row.col.f32.f16.f16.f32 "
                        "{%0,%1,%2,%3}, {%4,%5,%6,%7}, {%8,%9}, {%0,%1,%2,%3};"
                        : "+f"(acc[m8][n8][0]), "+f"(acc[m8][n8][1]),
                          "+f"(acc[m8][n8][2]), "+f"(acc[m8][n8][3])
                        : "r"(a[m8][0]), "r"(a[m8][1]), "r"(a[m8][2]), "r"(a[m8][3]),
                          "r"(b[n8][0]), "r"(b[n8][1]));
        }
        stage++; if (stage >= 3) stage = 0;
    }
    #undef ISSUE

    // ---- fused epilogue ----
    float2 biasv[4];
    int ncol[4];
    #pragma unroll
    for (int n8 = 0; n8 < 4; n8++) {
        const int n = nb * 128 + wn * 32 + n8 * 8 + 2 * qid;
        ncol[n8] = n;
        biasv[n8] = *reinterpret_cast<const float2*>(sub_b + n);
    }

    const int mbase = mt * 128 + wm * 64;
    #pragma unroll
    for (int m8 = 0; m8 < 4; m8++) {
        #pragma unroll
        for (int rh = 0; rh < 2; rh++) {
            const int m  = mbase + m8 * 16 + grp + rh * 8;
            const int b_ = m >> 13;
            const int l  = m & (LL - 1);
            float* ob = out_xup + ((size_t)b_ * (LL * UP) + (size_t)l * UP) * OUTC;
            const float* xr = x + (size_t)m * CC;
            #pragma unroll
            for (int n8 = 0; n8 < 4; n8++) {
                const int n = ncol[n8];
                const int u = n >> 8;
                const int c = n & 255;
                float2 xv = *reinterpret_cast<const float2*>(xr + c);
                float y0 = fmaf(acc[m8][n8][rh * 2 + 0], FC_GAIN, biasv[n8].x);
                float y1 = fmaf(acc[m8][n8][rh * 2 + 1], FC_GAIN, biasv[n8].y);
                float a0 = (y0 >= 0.0f ? y0 : 0.2f * y0) * SQRT2_F;
                float a1 = (y1 >= 0.0f ? y1 : 0.2f * y1) * SQRT2_F;
                float2 ov;
                ov.x = (xv.x + a0) * INV_SQRT2_F;
                ov.y = (xv.y + a1) * INV_SQRT2_F;
                *reinterpret_cast<float2*>(ob + (size_t)u * OUTC + c) = ov;
            }
        }
    }
}

// ---------------------------------------------------------------------------
extern "C" void kernel_launch(void* const* d_in, const int* in_sizes, int n_in,
                              void* d_out, int out_size)
{
    const float* x       = (const float*)d_in[0];
    const float* pc      = (const float*)d_in[1];
    const float* lff_w   = (const float*)d_in[2];
    const float* lff_b   = (const float*)d_in[3];
    const float* cpe_tab = (const float*)d_in[4];
    const float* sub_w   = (const float*)d_in[5];
    const float* sub_b   = (const float*)d_in[6];

    float* out_xup = (float*)d_out;
    float* out_pc  = (float*)d_out + (size_t)MM * UP * OUTC;

    pe_prep<<<MM / 16, 128>>>(pc, lff_w, lff_b, cpe_tab, out_pc);
    a_prep<<<dim3(8, MTILES), 128>>>(x);
    b_prep<<<dim3(NCHUNK, NBLKS), 128>>>(sub_w);
    gemm_hmma<<<dim3(NBLKS, MTILES), 256>>>(x, sub_b, out_xup);
}